// round 7
// baseline (speedup 1.0000x reference)
#include <cuda_runtime.h>
#include <cuda_bf16.h>
#include <cuda_fp16.h>

// Problem constants (shapes are fixed for this problem instance)
#define NN 50000
#define EE 800000

// ---------------- scratch (device globals; no runtime allocation) ------------
__device__ float  g_y[(size_t)NN * 256];   // layer-1 GEMM output [N][256]
__device__ float  g_h1[(size_t)NN * 128];  // layer-1 activations fp32
__device__ __half g_h1f[(size_t)NN * 128]; // layer-1 activations fp16 (agg copy)
__device__ float  g_h2[(size_t)NN * 128];
__device__ __half g_h2f[(size_t)NN * 128];
__device__ float  g_u[(size_t)NN * 128];   // aggregated input (u2 / u3)
__device__ float  g_y3[(size_t)NN * 64];   // layer-3 pre-lsm
__device__ int    g_deg[NN];
__device__ float  g_deginv[NN];
__device__ int    g_ptr[NN + 1];
__device__ int    g_fill[NN];
__device__ int    g_src[EE];
__device__ int    g_bsum[64];
__device__ int    g_i64;                   // 1 if edge_index is int64

// Pre-split weights (bf16 hi/lo planes).
// [0,32768): L1 [n=0..255][k=0..127]
// [32768,65536): L2cat [n=0..127][k=0..255]  (k<128: W2o, k>=128: W2r)
// [65536,98304): L3cat [n=0..127][k=0..255]  (n>=64 zero-padded)
__device__ __nv_bfloat16 g_Wh[98304];
__device__ __nv_bfloat16 g_Wl[98304];

// ---------------- zero + edge dtype detect -----------------------------------
__global__ void k_zero(const unsigned int* __restrict__ w, int n) {
    int i = blockIdx.x * blockDim.x + threadIdx.x;
    if (i < n) { g_deg[i] = 0; g_fill[i] = 0; }
    if (blockIdx.x == 0) {
        __shared__ int any;
        if (threadIdx.x == 0) any = 0;
        __syncthreads();
        for (int j = threadIdx.x; j < 1024; j += blockDim.x)
            if (w[2 * j + 1] != 0u) any = 1;
        __syncthreads();
        if (threadIdx.x == 0) g_i64 = any ? 0 : 1;
    }
}

__device__ __forceinline__ int edge_at(const void* ei, int idx) {
    if (g_i64) return (int)((const long long*)ei)[idx];
    return ((const int*)ei)[idx];
}

// ---------------- weight pre-split -------------------------------------------
__global__ void k_convW(const float* __restrict__ W1o, const float* __restrict__ W1r,
                        const float* __restrict__ W2o, const float* __restrict__ W2r,
                        const float* __restrict__ W3o, const float* __restrict__ W3r) {
    int i = blockIdx.x * blockDim.x + threadIdx.x;
    if (i >= 98304) return;
    float v;
    if (i < 32768) {
        int n = i >> 7, k = i & 127;
        v = (n < 128) ? W1o[(size_t)k * 128 + n] : W1r[(size_t)k * 128 + (n - 128)];
    } else if (i < 65536) {
        int rem = i - 32768;
        int n = rem >> 8, k = rem & 255;
        v = (k < 128) ? W2o[(size_t)k * 128 + n] : W2r[(size_t)(k - 128) * 128 + n];
    } else {
        int rem = i - 65536;
        int n = rem >> 8, k = rem & 255;
        if (n < 64)
            v = (k < 128) ? W3o[(size_t)k * 64 + n] : W3r[(size_t)(k - 128) * 64 + n];
        else
            v = 0.0f;
    }
    __nv_bfloat16 hi = __float2bfloat16(v);
    g_Wh[i] = hi;
    g_Wl[i] = __float2bfloat16(v - __bfloat162float(hi));
}

// ---------------- CSR build --------------------------------------------------
__global__ void k_hist(const void* __restrict__ ei, int E) {
    int i = blockIdx.x * blockDim.x + threadIdx.x;
    if (i < E) atomicAdd(&g_deg[edge_at(ei, E + i)], 1);
}

__global__ void k_scanA(int n) {
    __shared__ int s[1024];
    int i = blockIdx.x * 1024 + threadIdx.x;
    int v = (i < n) ? g_deg[i] : 0;
    if (i < n) g_deginv[i] = 1.0f / (float)(v + 1);
    s[threadIdx.x] = v;
    __syncthreads();
    for (int off = 1; off < 1024; off <<= 1) {
        int t = (threadIdx.x >= off) ? s[threadIdx.x - off] : 0;
        __syncthreads();
        s[threadIdx.x] += t;
        __syncthreads();
    }
    if (i < n) g_ptr[i + 1] = s[threadIdx.x];
    if (threadIdx.x == 1023) g_bsum[blockIdx.x] = s[1023];
}

__global__ void k_scanB(int nb) {
    __shared__ int s[64];
    int t = threadIdx.x;
    int v = (t < nb) ? g_bsum[t] : 0;
    s[t] = v;
    __syncthreads();
    for (int off = 1; off < 64; off <<= 1) {
        int u = (t >= off) ? s[t - off] : 0;
        __syncthreads();
        s[t] += u;
        __syncthreads();
    }
    if (t < nb) g_bsum[t] = s[t] - v;   // exclusive
}

__global__ void k_scanC(int n) {
    int i = blockIdx.x * blockDim.x + threadIdx.x;
    if (i == 0) g_ptr[0] = 0;
    if (i < n) g_ptr[i + 1] += g_bsum[i >> 10];
}

__global__ void k_fill(const void* __restrict__ ei, int E) {
    int i = blockIdx.x * blockDim.x + threadIdx.x;
    if (i < E) {
        int r = edge_at(ei, i);
        int c = edge_at(ei, E + i);
        int pos = g_ptr[c] + atomicAdd(&g_fill[c], 1);
        g_src[pos] = r;
    }
}

// ---------------- bf16 / fp16 helpers ----------------------------------------
__device__ __forceinline__ unsigned packbf(float x, float y) {
    unsigned r;
    asm("cvt.rn.bf16x2.f32 %0, %1, %2;" : "=r"(r) : "f"(y), "f"(x));
    return r;
}
__device__ __forceinline__ unsigned h2u(__half2 h) {
    union { __half2 h; unsigned u; } c;
    c.h = h;
    return c.u;
}
__device__ __forceinline__ void mma_bf16(float* c,
                                         unsigned a0, unsigned a1,
                                         unsigned a2, unsigned a3,
                                         unsigned b0, unsigned b1) {
    asm volatile(
        "mma.sync.aligned.m16n8k16.row.col.f32.bf16.bf16.f32 "
        "{%0,%1,%2,%3},{%4,%5,%6,%7},{%8,%9},{%0,%1,%2,%3};"
        : "+f"(c[0]), "+f"(c[1]), "+f"(c[2]), "+f"(c[3])
        : "r"(a0), "r"(a1), "r"(a2), "r"(a3), "r"(b0), "r"(b1));
}

#define SW 36   // smem stride (uints); fragment bank = 4*grp + q, conflict-free

// ---------------- shared GEMM core (bf16x3, block 128x128, 8 warps) ----------
// mode 1: A = xin (K=128), B off 0, N=256, out -> g_y
// mode 2: A = [g_u | g_h1] (K=256), B off 32768, N=128, epilogue b+relu ->
//         g_h2 fp32 + g_h2f fp16
// mode 3: A = [g_u | g_h2] (K=256), B off 65536, N=64 (padded 128), epilogue
//         b+relu -> g_y3
__global__ __launch_bounds__(256)
void k_gemm(const float* __restrict__ xin, const float* __restrict__ bias,
            int mode, int N) {
    extern __shared__ unsigned smu[];
    unsigned* As_h = smu;
    unsigned* As_l = smu + 128 * SW;
    unsigned* Bs_h = smu + 2 * 128 * SW;
    unsigned* Bs_l = smu + 3 * 128 * SW;

    const int tid = threadIdx.x;
    const int wid = tid >> 5;
    const int lane = tid & 31;
    const int grp = lane >> 2;
    const int q = lane & 3;
    const int warp_m = wid >> 2;    // 0..1
    const int warp_n = wid & 3;     // 0..3
    const int rowBase = blockIdx.y * 128;
    const int colBase = blockIdx.x * 128;

    const int K = (mode == 1) ? 128 : 256;
    const int Woff = (mode == 1) ? 0 : (mode == 2 ? 32768 : 65536);
    const int Wstride = (mode == 1) ? 128 : 256;
    const float* A0 = (mode == 1) ? xin : (const float*)g_u;
    const float* A1 = (mode == 2) ? (const float*)g_h1 : (const float*)g_h2;

    float acc[4][4][4];
#pragma unroll
    for (int i = 0; i < 4; i++)
#pragma unroll
        for (int j = 0; j < 4; j++)
#pragma unroll
            for (int v = 0; v < 4; v++) acc[i][j][v] = 0.0f;

    for (int kt = 0; kt < K; kt += 64) {
        const float* Asrc = (kt < 128) ? A0 : A1;
        int koff = kt & 127;
        // ---- A tile: load float4 along k, split to hi/lo bf16x2 planes ----
#pragma unroll
        for (int l = 0; l < 8; l++) {
            int idx = l * 256 + tid;
            int r = idx >> 4;
            int c = (idx & 15) * 4;
            int grow = rowBase + r;
            float4 v = make_float4(0.f, 0.f, 0.f, 0.f);
            if (grow < N)
                v = *(const float4*)(Asrc + (size_t)grow * 128 + koff + c);
            unsigned h0 = packbf(v.x, v.y);
            unsigned h1 = packbf(v.z, v.w);
            float lx = v.x - __uint_as_float(h0 << 16);
            float ly = v.y - __uint_as_float(h0 & 0xffff0000u);
            float lz = v.z - __uint_as_float(h1 << 16);
            float lw = v.w - __uint_as_float(h1 & 0xffff0000u);
            unsigned l0 = packbf(lx, ly);
            unsigned l1 = packbf(lz, lw);
            int off = r * SW + (c >> 1);
            *(uint2*)&As_h[off] = make_uint2(h0, h1);
            *(uint2*)&As_l[off] = make_uint2(l0, l1);
        }
        // ---- B tile: uint4 copies from pre-split g_Wh/g_Wl ----
#pragma unroll
        for (int l = 0; l < 8; l++) {
            int idx = l * 256 + tid;
            int plane = idx >> 10;
            int rem = idx & 1023;
            int n = rem >> 3;
            int jj = rem & 7;
            const __nv_bfloat16* Wp = plane ? g_Wl : g_Wh;
            const uint4* rowp =
                (const uint4*)(Wp + (size_t)Woff + (size_t)(colBase + n) * Wstride);
            uint4 v = rowp[(kt >> 3) + jj];
            unsigned* Bd = plane ? Bs_l : Bs_h;
            *(uint4*)&Bd[n * SW + jj * 4] = v;
        }
        __syncthreads();

#pragma unroll
        for (int ks = 0; ks < 4; ks++) {
            int kb = ks * 8;
            unsigned ah[4][4], al[4][4], bh[4][2], bl[4][2];
#pragma unroll
            for (int mf = 0; mf < 4; mf++) {
                int base = (warp_m * 64 + mf * 16 + grp) * SW + kb + q;
                ah[mf][0] = As_h[base];
                ah[mf][1] = As_h[base + 8 * SW];
                ah[mf][2] = As_h[base + 4];
                ah[mf][3] = As_h[base + 4 + 8 * SW];
                al[mf][0] = As_l[base];
                al[mf][1] = As_l[base + 8 * SW];
                al[mf][2] = As_l[base + 4];
                al[mf][3] = As_l[base + 4 + 8 * SW];
            }
#pragma unroll
            for (int nf = 0; nf < 4; nf++) {
                int cb = (warp_n * 32 + nf * 8 + grp) * SW + kb + q;
                bh[nf][0] = Bs_h[cb];
                bh[nf][1] = Bs_h[cb + 4];
                bl[nf][0] = Bs_l[cb];
                bl[nf][1] = Bs_l[cb + 4];
            }
#pragma unroll
            for (int mf = 0; mf < 4; mf++)
#pragma unroll
                for (int nf = 0; nf < 4; nf++) {
                    float* c = acc[mf][nf];
                    mma_bf16(c, ah[mf][0], ah[mf][1], ah[mf][2], ah[mf][3],
                             bh[nf][0], bh[nf][1]);
                    mma_bf16(c, ah[mf][0], ah[mf][1], ah[mf][2], ah[mf][3],
                             bl[nf][0], bl[nf][1]);
                    mma_bf16(c, al[mf][0], al[mf][1], al[mf][2], al[mf][3],
                             bh[nf][0], bh[nf][1]);
                }
        }
        __syncthreads();
    }

    // ---- epilogue ----
#pragma unroll
    for (int mf = 0; mf < 4; mf++) {
        int row0 = rowBase + warp_m * 64 + mf * 16 + grp;
        int row1 = row0 + 8;
#pragma unroll
        for (int nf = 0; nf < 4; nf++) {
            int col = colBase + warp_n * 32 + nf * 8 + 2 * q;
            float* c = acc[mf][nf];
            if (mode == 1) {
                if (row0 < N)
                    *(float2*)(g_y + (size_t)row0 * 256 + col) = make_float2(c[0], c[1]);
                if (row1 < N)
                    *(float2*)(g_y + (size_t)row1 * 256 + col) = make_float2(c[2], c[3]);
            } else if (mode == 2) {
                float b0 = bias[col], b1v = bias[col + 1];
                float v0 = fmaxf(c[0] + b0, 0.f), v1 = fmaxf(c[1] + b1v, 0.f);
                float v2 = fmaxf(c[2] + b0, 0.f), v3 = fmaxf(c[3] + b1v, 0.f);
                if (row0 < N) {
                    *(float2*)(g_h2 + (size_t)row0 * 128 + col) = make_float2(v0, v1);
                    *(__half2*)(g_h2f + (size_t)row0 * 128 + col) =
                        __floats2half2_rn(v0, v1);
                }
                if (row1 < N) {
                    *(float2*)(g_h2 + (size_t)row1 * 128 + col) = make_float2(v2, v3);
                    *(__half2*)(g_h2f + (size_t)row1 * 128 + col) =
                        __floats2half2_rn(v2, v3);
                }
            } else {
                if (col < 64) {
                    float b0 = bias[col], b1v = bias[col + 1];
                    if (row0 < N)
                        *(float2*)(g_y3 + (size_t)row0 * 64 + col) =
                            make_float2(fmaxf(c[0] + b0, 0.f), fmaxf(c[1] + b1v, 0.f));
                    if (row1 < N)
                        *(float2*)(g_y3 + (size_t)row1 * 64 + col) =
                            make_float2(fmaxf(c[2] + b0, 0.f), fmaxf(c[3] + b1v, 0.f));
                }
            }
        }
    }
}

// ---------------- Layer-1 aggregation (fp32 reads of g_y) --------------------
// g_h1 = relu( deg_inv*(sum y_out[src] + y_out[w]) + y_root[w] + b ), + fp16 copy
__global__ __launch_bounds__(256)
void k_agg128(const float* __restrict__ bias, int N) {
    int w = (blockIdx.x * blockDim.x + threadIdx.x) >> 5;
    int lane = threadIdx.x & 31;
    if (w >= N) return;
    const float* Y = (const float*)g_y;
    size_t base = (size_t)w * 256;
    float4 acc = *(const float4*)(Y + base + lane * 4);
    int p0 = g_ptr[w], p1 = g_ptr[w + 1];
    int e = p0;
    for (; e + 2 <= p1; e += 2) {
        int r0 = g_src[e], r1 = g_src[e + 1];
        float4 t0 = *(const float4*)(Y + (size_t)r0 * 256 + lane * 4);
        float4 t1 = *(const float4*)(Y + (size_t)r1 * 256 + lane * 4);
        acc.x += t0.x + t1.x; acc.y += t0.y + t1.y;
        acc.z += t0.z + t1.z; acc.w += t0.w + t1.w;
    }
    if (e < p1) {
        float4 t0 = *(const float4*)(Y + (size_t)g_src[e] * 256 + lane * 4);
        acc.x += t0.x; acc.y += t0.y; acc.z += t0.z; acc.w += t0.w;
    }
    float dinv = g_deginv[w];
    float4 rt = *(const float4*)(Y + base + 128 + lane * 4);
    float4 bv = *(const float4*)(bias + lane * 4);
    float4 o;
    o.x = fmaxf(acc.x * dinv + rt.x + bv.x, 0.f);
    o.y = fmaxf(acc.y * dinv + rt.y + bv.y, 0.f);
    o.z = fmaxf(acc.z * dinv + rt.z + bv.z, 0.f);
    o.w = fmaxf(acc.w * dinv + rt.w + bv.w, 0.f);
    *(float4*)(g_h1 + (size_t)w * 128 + lane * 4) = o;
    *(uint2*)(g_h1f + (size_t)w * 128 + lane * 4) =
        make_uint2(h2u(__floats2half2_rn(o.x, o.y)),
                   h2u(__floats2half2_rn(o.z, o.w)));
}

// ---------------- Pre-aggregation (fp16 edge reads, positive values) ---------
// g_u = deg_inv * ( h_self(fp32) + sum h_f16[src] )
__global__ __launch_bounds__(256)
void k_aggpre(int layer, int N) {
    int w = (blockIdx.x * blockDim.x + threadIdx.x) >> 5;
    int lane = threadIdx.x & 31;
    if (w >= N) return;
    const float* Hs = (layer == 2) ? (const float*)g_h1 : (const float*)g_h2;
    const __half* Hf = (layer == 2) ? (const __half*)g_h1f : (const __half*)g_h2f;
    float4 acc = *(const float4*)(Hs + (size_t)w * 128 + lane * 4);  // self
    int p0 = g_ptr[w], p1 = g_ptr[w + 1];
    int e = p0;
    for (; e + 2 <= p1; e += 2) {
        int r0 = g_src[e], r1 = g_src[e + 1];
        uint2 a = *(const uint2*)(Hf + (size_t)r0 * 128 + lane * 4);
        uint2 b = *(const uint2*)(Hf + (size_t)r1 * 128 + lane * 4);
        float2 a0 = __half22float2(*(__half2*)&a.x);
        float2 a1 = __half22float2(*(__half2*)&a.y);
        float2 b0 = __half22float2(*(__half2*)&b.x);
        float2 b1 = __half22float2(*(__half2*)&b.y);
        acc.x += a0.x + b0.x; acc.y += a0.y + b0.y;
        acc.z += a1.x + b1.x; acc.w += a1.y + b1.y;
    }
    if (e < p1) {
        uint2 a = *(const uint2*)(Hf + (size_t)g_src[e] * 128 + lane * 4);
        float2 a0 = __half22float2(*(__half2*)&a.x);
        float2 a1 = __half22float2(*(__half2*)&a.y);
        acc.x += a0.x; acc.y += a0.y; acc.z += a1.x; acc.w += a1.y;
    }
    float dinv = g_deginv[w];
    acc.x *= dinv; acc.y *= dinv; acc.z *= dinv; acc.w *= dinv;
    *(float4*)(g_u + (size_t)w * 128 + lane * 4) = acc;
}

// ---------------- log_softmax over 64 cols -----------------------------------
__global__ __launch_bounds__(256)
void k_lsm(float* __restrict__ Out, int N) {
    int w = (blockIdx.x * blockDim.x + threadIdx.x) >> 5;
    int lane = threadIdx.x & 31;
    if (w >= N) return;
    float2 v = *(const float2*)(g_y3 + (size_t)w * 64 + lane * 2);
    float m = fmaxf(v.x, v.y);
#pragma unroll
    for (int o = 16; o; o >>= 1) m = fmaxf(m, __shfl_xor_sync(0xffffffffu, m, o));
    float s = expf(v.x - m) + expf(v.y - m);
#pragma unroll
    for (int o = 16; o; o >>= 1) s += __shfl_xor_sync(0xffffffffu, s, o);
    float l = m + logf(s);
    *(float2*)(Out + (size_t)w * 64 + lane * 2) = make_float2(v.x - l, v.y - l);
}

// ---------------- driver -----------------------------------------------------
extern "C" void kernel_launch(void* const* d_in, const int* in_sizes, int n_in,
                              void* d_out, int out_size) {
    const float* x   = (const float*)d_in[0];
    const void*  ei  = d_in[1];
    const float* W1o = (const float*)d_in[2];
    const float* b1  = (const float*)d_in[3];
    const float* W1r = (const float*)d_in[4];
    const float* W2o = (const float*)d_in[5];
    const float* b2  = (const float*)d_in[6];
    const float* W2r = (const float*)d_in[7];
    const float* W3o = (const float*)d_in[8];
    const float* b3  = (const float*)d_in[9];
    const float* W3r = (const float*)d_in[10];
    float* out = (float*)d_out;

    int N = in_sizes[0] / 128;
    int E = in_sizes[1] / 2;

    const int smemBytes = 4 * 128 * SW * 4;   // 73728
    cudaFuncSetAttribute(k_gemm, cudaFuncAttributeMaxDynamicSharedMemorySize,
                         smemBytes);

    // Weight pre-split + CSR build
    k_convW<<<(98304 + 255) / 256, 256>>>(W1o, W1r, W2o, W2r, W3o, W3r);
    k_zero<<<(N + 255) / 256, 256>>>((const unsigned int*)ei, N);
    k_hist<<<(E + 255) / 256, 256>>>(ei, E);
    int nb = (N + 1023) / 1024;
    k_scanA<<<nb, 1024>>>(N);
    k_scanB<<<1, 64>>>(nb);
    k_scanC<<<(N + 255) / 256, 256>>>(N);
    k_fill<<<(E + 255) / 256, 256>>>(ei, E);

    int aggBlocks = (N * 32 + 255) / 256;
    dim3 g2(2, (N + 127) / 128);
    dim3 g1(1, (N + 127) / 128);

    // Layer 1: GEMM (K=128, N=256) then fp32 aggregation (+ fp16 copy)
    k_gemm<<<g2, 256, smemBytes>>>(x, b1, 1, N);
    k_agg128<<<aggBlocks, 256>>>(b1, N);
    // Layer 2: fp16 pre-aggregation, then fused GEMM (K=256) + bias + relu
    k_aggpre<<<aggBlocks, 256>>>(2, N);
    k_gemm<<<g1, 256, smemBytes>>>(x, b2, 2, N);
    // Layer 3: fp16 pre-aggregation, fused GEMM (K=256, N=64) + bias + relu
    k_aggpre<<<aggBlocks, 256>>>(3, N);
    k_gemm<<<g1, 256, smemBytes>>>(x, b3, 3, N);
    // log_softmax
    k_lsm<<<aggBlocks, 256>>>(out, N);
}

// round 8
// speedup vs baseline: 1.0807x; 1.0807x over previous
#include <cuda_runtime.h>
#include <cuda_bf16.h>
#include <cuda_fp16.h>

// Problem constants (shapes are fixed for this problem instance)
#define NN 50000
#define EE 800000

// ---------------- scratch (device globals; no runtime allocation) ------------
__device__ float  g_y[(size_t)NN * 256];   // GEMM output [N][2*nhalf]
__device__ __half g_yf[(size_t)NN * 128];  // fp16 copy of out-half (gathered)
__device__ float  g_h[(size_t)NN * 128];   // layer activations
__device__ int    g_deg[NN];
__device__ float  g_deginv[NN];
__device__ int    g_ptr[NN + 1];
__device__ int    g_fill[NN];
__device__ int    g_src[EE];
__device__ int    g_bsum[64];
__device__ int    g_i64;                   // 1 if edge_index is int64

// Pre-split weights (bf16 hi/lo planes), layout [n][k=128] per layer.
// L1: n in [0,256) off 0; L2: off 32768; L3: n in [0,128) off 65536.
__device__ __nv_bfloat16 g_Wh[81920];
__device__ __nv_bfloat16 g_Wl[81920];

// ---------------- zero + edge dtype detect -----------------------------------
__global__ void k_zero(const unsigned int* __restrict__ w, int n) {
    int i = blockIdx.x * blockDim.x + threadIdx.x;
    if (i < n) { g_deg[i] = 0; g_fill[i] = 0; }
    if (blockIdx.x == 0) {
        __shared__ int any;
        if (threadIdx.x == 0) any = 0;
        __syncthreads();
        for (int j = threadIdx.x; j < 1024; j += blockDim.x)
            if (w[2 * j + 1] != 0u) any = 1;
        __syncthreads();
        if (threadIdx.x == 0) g_i64 = any ? 0 : 1;
    }
}

__device__ __forceinline__ int edge_at(const void* ei, int idx) {
    if (g_i64) return (int)((const long long*)ei)[idx];
    return ((const int*)ei)[idx];
}

// ---------------- weight pre-split -------------------------------------------
__global__ void k_convW(const float* __restrict__ W1o, const float* __restrict__ W1r,
                        const float* __restrict__ W2o, const float* __restrict__ W2r,
                        const float* __restrict__ W3o, const float* __restrict__ W3r) {
    int i = blockIdx.x * blockDim.x + threadIdx.x;
    if (i >= 81920) return;
    const float* Wo;
    const float* Wr;
    int nh, rem;
    if (i < 32768)      { Wo = W1o; Wr = W1r; nh = 128; rem = i; }
    else if (i < 65536) { Wo = W2o; Wr = W2r; nh = 128; rem = i - 32768; }
    else                { Wo = W3o; Wr = W3r; nh = 64;  rem = i - 65536; }
    int n = rem >> 7;
    int k = rem & 127;
    float v = (n < nh) ? Wo[(size_t)k * nh + n] : Wr[(size_t)k * nh + (n - nh)];
    __nv_bfloat16 hi = __float2bfloat16(v);
    g_Wh[i] = hi;
    g_Wl[i] = __float2bfloat16(v - __bfloat162float(hi));
}

// ---------------- CSR build --------------------------------------------------
__global__ void k_hist(const void* __restrict__ ei, int E) {
    int i = blockIdx.x * blockDim.x + threadIdx.x;
    if (i < E) atomicAdd(&g_deg[edge_at(ei, E + i)], 1);
}

__global__ void k_scanA(int n) {
    __shared__ int s[1024];
    int i = blockIdx.x * 1024 + threadIdx.x;
    int v = (i < n) ? g_deg[i] : 0;
    if (i < n) g_deginv[i] = 1.0f / (float)(v + 1);
    s[threadIdx.x] = v;
    __syncthreads();
    for (int off = 1; off < 1024; off <<= 1) {
        int t = (threadIdx.x >= off) ? s[threadIdx.x - off] : 0;
        __syncthreads();
        s[threadIdx.x] += t;
        __syncthreads();
    }
    if (i < n) g_ptr[i + 1] = s[threadIdx.x];
    if (threadIdx.x == 1023) g_bsum[blockIdx.x] = s[1023];
}

__global__ void k_scanB(int nb) {
    __shared__ int s[64];
    int t = threadIdx.x;
    int v = (t < nb) ? g_bsum[t] : 0;
    s[t] = v;
    __syncthreads();
    for (int off = 1; off < 64; off <<= 1) {
        int u = (t >= off) ? s[t - off] : 0;
        __syncthreads();
        s[t] += u;
        __syncthreads();
    }
    if (t < nb) g_bsum[t] = s[t] - v;   // exclusive
}

__global__ void k_scanC(int n) {
    int i = blockIdx.x * blockDim.x + threadIdx.x;
    if (i == 0) g_ptr[0] = 0;
    if (i < n) g_ptr[i + 1] += g_bsum[i >> 10];
}

__global__ void k_fill(const void* __restrict__ ei, int E) {
    int i = blockIdx.x * blockDim.x + threadIdx.x;
    if (i < E) {
        int r = edge_at(ei, i);
        int c = edge_at(ei, E + i);
        int pos = g_ptr[c] + atomicAdd(&g_fill[c], 1);
        g_src[pos] = r;
    }
}

// ---------------- bf16 / fp16 helpers ----------------------------------------
__device__ __forceinline__ unsigned packbf(float x, float y) {
    unsigned r;
    asm("cvt.rn.bf16x2.f32 %0, %1, %2;" : "=r"(r) : "f"(y), "f"(x));
    return r;
}
__device__ __forceinline__ unsigned h2u(__half2 h) {
    union { __half2 h; unsigned u; } c;
    c.h = h;
    return c.u;
}
__device__ __forceinline__ void mma_bf16(float* c,
                                         unsigned a0, unsigned a1,
                                         unsigned a2, unsigned a3,
                                         unsigned b0, unsigned b1) {
    asm volatile(
        "mma.sync.aligned.m16n8k16.row.col.f32.bf16.bf16.f32 "
        "{%0,%1,%2,%3},{%4,%5,%6,%7},{%8,%9},{%0,%1,%2,%3};"
        : "+f"(c[0]), "+f"(c[1]), "+f"(c[2]), "+f"(c[3])
        : "r"(a0), "r"(a1), "r"(a2), "r"(a3), "r"(b0), "r"(b1));
}

#define SW 36   // smem stride (uints); fragment bank = 4*grp + q, conflict-free

// ---------------- GEMM: g_y[N][2*nhalf] = A[N][128] @ [Wout | Wroot] ---------
// bf16x3 compensated tensor-core GEMM. Block tile 128x128, BK=64, 8 warps
// (2x4), warp tile 64x32, mma m16n8k16. Epilogue also writes fp16 copy of
// the out-half columns (col < nhalf) into g_yf for the edge gather.
__global__ __launch_bounds__(256)
void k_gemm_bf(const float* __restrict__ xin, int useH, int Woff,
               int nhalf, int N) {
    extern __shared__ unsigned smu[];
    unsigned* As_h = smu;
    unsigned* As_l = smu + 128 * SW;
    unsigned* Bs_h = smu + 2 * 128 * SW;
    unsigned* Bs_l = smu + 3 * 128 * SW;

    const float* A = useH ? (const float*)g_h : xin;

    const int tid = threadIdx.x;
    const int wid = tid >> 5;
    const int lane = tid & 31;
    const int grp = lane >> 2;
    const int q = lane & 3;
    const int warp_m = wid >> 2;    // 0..1
    const int warp_n = wid & 3;     // 0..3
    const int rowBase = blockIdx.y * 128;
    const int colBase = blockIdx.x * 128;
    const int Nc = 2 * nhalf;

    float acc[4][4][4];
#pragma unroll
    for (int i = 0; i < 4; i++)
#pragma unroll
        for (int j = 0; j < 4; j++)
#pragma unroll
            for (int v = 0; v < 4; v++) acc[i][j][v] = 0.0f;

    for (int kt = 0; kt < 128; kt += 64) {
        // ---- A tile: load float4 along k, split to hi/lo bf16x2 planes ----
#pragma unroll
        for (int l = 0; l < 8; l++) {
            int idx = l * 256 + tid;
            int r = idx >> 4;
            int c = (idx & 15) * 4;
            int grow = rowBase + r;
            float4 v = make_float4(0.f, 0.f, 0.f, 0.f);
            if (grow < N) v = *(const float4*)(A + (size_t)grow * 128 + kt + c);
            unsigned h0 = packbf(v.x, v.y);
            unsigned h1 = packbf(v.z, v.w);
            float lx = v.x - __uint_as_float(h0 << 16);
            float ly = v.y - __uint_as_float(h0 & 0xffff0000u);
            float lz = v.z - __uint_as_float(h1 << 16);
            float lw = v.w - __uint_as_float(h1 & 0xffff0000u);
            unsigned l0 = packbf(lx, ly);
            unsigned l1 = packbf(lz, lw);
            int off = r * SW + (c >> 1);
            *(uint2*)&As_h[off] = make_uint2(h0, h1);
            *(uint2*)&As_l[off] = make_uint2(l0, l1);
        }
        // ---- B tile: uint4 copies from pre-split g_Wh/g_Wl ----
#pragma unroll
        for (int l = 0; l < 8; l++) {
            int idx = l * 256 + tid;
            int plane = idx >> 10;
            int rem = idx & 1023;
            int n = rem >> 3;
            int jj = rem & 7;
            const __nv_bfloat16* Wp = plane ? g_Wl : g_Wh;
            const uint4* rowp =
                (const uint4*)(Wp + (size_t)(Woff + (colBase + n) * 128));
            uint4 v = rowp[(kt >> 3) + jj];
            unsigned* Bd = plane ? Bs_l : Bs_h;
            *(uint4*)&Bd[n * SW + jj * 4] = v;
        }
        __syncthreads();

#pragma unroll
        for (int ks = 0; ks < 4; ks++) {
            int kb = ks * 8;
            unsigned ah[4][4], al[4][4], bh[4][2], bl[4][2];
#pragma unroll
            for (int mf = 0; mf < 4; mf++) {
                int base = (warp_m * 64 + mf * 16 + grp) * SW + kb + q;
                ah[mf][0] = As_h[base];
                ah[mf][1] = As_h[base + 8 * SW];
                ah[mf][2] = As_h[base + 4];
                ah[mf][3] = As_h[base + 4 + 8 * SW];
                al[mf][0] = As_l[base];
                al[mf][1] = As_l[base + 8 * SW];
                al[mf][2] = As_l[base + 4];
                al[mf][3] = As_l[base + 4 + 8 * SW];
            }
#pragma unroll
            for (int nf = 0; nf < 4; nf++) {
                int cb = (warp_n * 32 + nf * 8 + grp) * SW + kb + q;
                bh[nf][0] = Bs_h[cb];
                bh[nf][1] = Bs_h[cb + 4];
                bl[nf][0] = Bs_l[cb];
                bl[nf][1] = Bs_l[cb + 4];
            }
#pragma unroll
            for (int mf = 0; mf < 4; mf++)
#pragma unroll
                for (int nf = 0; nf < 4; nf++) {
                    float* c = acc[mf][nf];
                    mma_bf16(c, ah[mf][0], ah[mf][1], ah[mf][2], ah[mf][3],
                             bh[nf][0], bh[nf][1]);
                    mma_bf16(c, ah[mf][0], ah[mf][1], ah[mf][2], ah[mf][3],
                             bl[nf][0], bl[nf][1]);
                    mma_bf16(c, al[mf][0], al[mf][1], al[mf][2], al[mf][3],
                             bh[nf][0], bh[nf][1]);
                }
        }
        __syncthreads();
    }

    // ---- epilogue: fp32 to g_y; out-half also fp16 to g_yf ----
#pragma unroll
    for (int mf = 0; mf < 4; mf++) {
        int row0 = rowBase + warp_m * 64 + mf * 16 + grp;
        int row1 = row0 + 8;
#pragma unroll
        for (int nf = 0; nf < 4; nf++) {
            int col = colBase + warp_n * 32 + nf * 8 + 2 * q;
            float* c = acc[mf][nf];
            if (row0 < N) {
                *(float2*)(g_y + (size_t)row0 * Nc + col) = make_float2(c[0], c[1]);
                if (col < nhalf)
                    *(unsigned*)(g_yf + (size_t)row0 * nhalf + col) =
                        h2u(__floats2half2_rn(c[0], c[1]));
            }
            if (row1 < N) {
                *(float2*)(g_y + (size_t)row1 * Nc + col) = make_float2(c[2], c[3]);
                if (col < nhalf)
                    *(unsigned*)(g_yf + (size_t)row1 * nhalf + col) =
                        h2u(__floats2half2_rn(c[2], c[3]));
            }
        }
    }
}

// ---------------- Aggregation (warp per node), 128 cols, fp16 gather ---------
// g_h = relu( deg_inv*(sum yf[src] + y_out[w]) + y_root[w] + b )
__global__ __launch_bounds__(256)
void k_agg128(const float* __restrict__ bias, int N) {
    int w = (blockIdx.x * blockDim.x + threadIdx.x) >> 5;
    int lane = threadIdx.x & 31;
    if (w >= N) return;
    const float* Y = (const float*)g_y;
    const __half* Yf = (const __half*)g_yf;
    size_t base = (size_t)w * 256;
    float4 acc = *(const float4*)(Y + base + lane * 4);   // self loop (exact)
    int p0 = g_ptr[w], p1 = g_ptr[w + 1];
    int e = p0;
    for (; e + 4 <= p1; e += 4) {
        int r0 = g_src[e], r1 = g_src[e + 1], r2 = g_src[e + 2], r3 = g_src[e + 3];
        uint2 a = *(const uint2*)(Yf + (size_t)r0 * 128 + lane * 4);
        uint2 b = *(const uint2*)(Yf + (size_t)r1 * 128 + lane * 4);
        uint2 cc = *(const uint2*)(Yf + (size_t)r2 * 128 + lane * 4);
        uint2 d = *(const uint2*)(Yf + (size_t)r3 * 128 + lane * 4);
        float2 a0 = __half22float2(*(__half2*)&a.x), a1 = __half22float2(*(__half2*)&a.y);
        float2 b0 = __half22float2(*(__half2*)&b.x), b1 = __half22float2(*(__half2*)&b.y);
        float2 c0 = __half22float2(*(__half2*)&cc.x), c1 = __half22float2(*(__half2*)&cc.y);
        float2 d0 = __half22float2(*(__half2*)&d.x), d1 = __half22float2(*(__half2*)&d.y);
        acc.x += (a0.x + b0.x) + (c0.x + d0.x);
        acc.y += (a0.y + b0.y) + (c0.y + d0.y);
        acc.z += (a1.x + b1.x) + (c1.x + d1.x);
        acc.w += (a1.y + b1.y) + (c1.y + d1.y);
    }
    for (; e < p1; e++) {
        uint2 a = *(const uint2*)(Yf + (size_t)g_src[e] * 128 + lane * 4);
        float2 a0 = __half22float2(*(__half2*)&a.x), a1 = __half22float2(*(__half2*)&a.y);
        acc.x += a0.x; acc.y += a0.y; acc.z += a1.x; acc.w += a1.y;
    }
    float dinv = g_deginv[w];
    float4 rt = *(const float4*)(Y + base + 128 + lane * 4);
    float4 bv = *(const float4*)(bias + lane * 4);
    float4 o;
    o.x = fmaxf(acc.x * dinv + rt.x + bv.x, 0.f);
    o.y = fmaxf(acc.y * dinv + rt.y + bv.y, 0.f);
    o.z = fmaxf(acc.z * dinv + rt.z + bv.z, 0.f);
    o.w = fmaxf(acc.w * dinv + rt.w + bv.w, 0.f);
    *(float4*)(g_h + (size_t)w * 128 + lane * 4) = o;
}

// ---------------- Aggregation 64 cols + fused log_softmax, fp16 gather -------
__global__ __launch_bounds__(256)
void k_agg64_lsm(const float* __restrict__ bias, float* __restrict__ Out, int N) {
    int w = (blockIdx.x * blockDim.x + threadIdx.x) >> 5;
    int lane = threadIdx.x & 31;
    if (w >= N) return;
    const float* Y = (const float*)g_y;
    const __half* Yf = (const __half*)g_yf;
    size_t base = (size_t)w * 128;
    float2 acc = *(const float2*)(Y + base + lane * 2);   // self loop (exact)
    int p0 = g_ptr[w], p1 = g_ptr[w + 1];
    int e = p0;
    for (; e + 4 <= p1; e += 4) {
        int r0 = g_src[e], r1 = g_src[e + 1], r2 = g_src[e + 2], r3 = g_src[e + 3];
        unsigned a = *(const unsigned*)(Yf + (size_t)r0 * 64 + lane * 2);
        unsigned b = *(const unsigned*)(Yf + (size_t)r1 * 64 + lane * 2);
        unsigned c = *(const unsigned*)(Yf + (size_t)r2 * 64 + lane * 2);
        unsigned d = *(const unsigned*)(Yf + (size_t)r3 * 64 + lane * 2);
        float2 a0 = __half22float2(*(__half2*)&a);
        float2 b0 = __half22float2(*(__half2*)&b);
        float2 c0 = __half22float2(*(__half2*)&c);
        float2 d0 = __half22float2(*(__half2*)&d);
        acc.x += (a0.x + b0.x) + (c0.x + d0.x);
        acc.y += (a0.y + b0.y) + (c0.y + d0.y);
    }
    for (; e < p1; e++) {
        unsigned a = *(const unsigned*)(Yf + (size_t)g_src[e] * 64 + lane * 2);
        float2 a0 = __half22float2(*(__half2*)&a);
        acc.x += a0.x; acc.y += a0.y;
    }
    float dinv = g_deginv[w];
    float2 rt = *(const float2*)(Y + base + 64 + lane * 2);
    float2 bv = *(const float2*)(bias + lane * 2);
    float v0 = fmaxf(acc.x * dinv + rt.x + bv.x, 0.f);
    float v1 = fmaxf(acc.y * dinv + rt.y + bv.y, 0.f);
    float m = fmaxf(v0, v1);
#pragma unroll
    for (int o = 16; o; o >>= 1) m = fmaxf(m, __shfl_xor_sync(0xffffffffu, m, o));
    float s = expf(v0 - m) + expf(v1 - m);
#pragma unroll
    for (int o = 16; o; o >>= 1) s += __shfl_xor_sync(0xffffffffu, s, o);
    float l = m + logf(s);
    *(float2*)(Out + (size_t)w * 64 + lane * 2) = make_float2(v0 - l, v1 - l);
}

// ---------------- driver -----------------------------------------------------
extern "C" void kernel_launch(void* const* d_in, const int* in_sizes, int n_in,
                              void* d_out, int out_size) {
    const float* x   = (const float*)d_in[0];
    const void*  ei  = d_in[1];
    const float* W1o = (const float*)d_in[2];
    const float* b1  = (const float*)d_in[3];
    const float* W1r = (const float*)d_in[4];
    const float* W2o = (const float*)d_in[5];
    const float* b2  = (const float*)d_in[6];
    const float* W2r = (const float*)d_in[7];
    const float* W3o = (const float*)d_in[8];
    const float* b3  = (const float*)d_in[9];
    const float* W3r = (const float*)d_in[10];
    float* out = (float*)d_out;

    int N = in_sizes[0] / 128;
    int E = in_sizes[1] / 2;

    const int smemBytes = 4 * 128 * SW * 4;   // 73728
    cudaFuncSetAttribute(k_gemm_bf, cudaFuncAttributeMaxDynamicSharedMemorySize,
                         smemBytes);

    // Weight pre-split + CSR build (reused by all 3 layers)
    k_convW<<<(81920 + 255) / 256, 256>>>(W1o, W1r, W2o, W2r, W3o, W3r);
    k_zero<<<(N + 255) / 256, 256>>>((const unsigned int*)ei, N);
    k_hist<<<(E + 255) / 256, 256>>>(ei, E);
    int nb = (N + 1023) / 1024;
    k_scanA<<<nb, 1024>>>(N);
    k_scanB<<<1, 64>>>(nb);
    k_scanC<<<(N + 255) / 256, 256>>>(N);
    k_fill<<<(E + 255) / 256, 256>>>(ei, E);

    int aggBlocks = (N * 32 + 255) / 256;
    dim3 g2(2, (N + 127) / 128);
    dim3 g1(1, (N + 127) / 128);

    // Layer 1
    k_gemm_bf<<<g2, 256, smemBytes>>>(x, 0, 0, 128, N);
    k_agg128<<<aggBlocks, 256>>>(b1, N);
    // Layer 2
    k_gemm_bf<<<g2, 256, smemBytes>>>(x, 1, 32768, 128, N);
    k_agg128<<<aggBlocks, 256>>>(b2, N);
    // Layer 3 (+ fused log_softmax)
    k_gemm_bf<<<g1, 256, smemBytes>>>(x, 1, 65536, 64, N);
    k_agg64_lsm<<<aggBlocks, 256>>>(b3, out, N);
}

// round 9
// speedup vs baseline: 1.1771x; 1.0892x over previous
#include <cuda_runtime.h>
#include <cuda_bf16.h>

// Problem constants (shapes are fixed for this problem instance)
#define NN 50000
#define EE 800000

// ---------------- scratch (device globals; no runtime allocation) ------------
__device__ float g_y[(size_t)NN * 256];   // GEMM output [N][2*nhalf], nhalf<=128
__device__ float g_h[(size_t)NN * 128];   // layer activations
__device__ int   g_deg[NN];
__device__ float g_deginv[NN];
__device__ int   g_ptr[NN + 1];
__device__ int   g_fill[NN];
__device__ int   g_src[EE];
__device__ int   g_bsum[64];
__device__ int   g_i64;                   // 1 if edge_index is int64

// Pre-split weights (bf16 hi/lo planes), layout [n][k=128] per layer.
// L1: n in [0,256) off 0; L2: off 32768; L3: n in [0,128) off 65536.
__device__ __nv_bfloat16 g_Wh[81920];
__device__ __nv_bfloat16 g_Wl[81920];

// ---------------- zero + edge dtype detect -----------------------------------
__global__ void k_zero(const unsigned int* __restrict__ w, int n) {
    int i = blockIdx.x * blockDim.x + threadIdx.x;
    if (i < n) { g_deg[i] = 0; g_fill[i] = 0; }
    if (blockIdx.x == 0) {
        __shared__ int any;
        if (threadIdx.x == 0) any = 0;
        __syncthreads();
        for (int j = threadIdx.x; j < 1024; j += blockDim.x)
            if (w[2 * j + 1] != 0u) any = 1;
        __syncthreads();
        if (threadIdx.x == 0) g_i64 = any ? 0 : 1;
    }
}

__device__ __forceinline__ int edge_at(const void* ei, int idx) {
    if (g_i64) return (int)((const long long*)ei)[idx];
    return ((const int*)ei)[idx];
}

// ---------------- weight pre-split -------------------------------------------
__global__ void k_convW(const float* __restrict__ W1o, const float* __restrict__ W1r,
                        const float* __restrict__ W2o, const float* __restrict__ W2r,
                        const float* __restrict__ W3o, const float* __restrict__ W3r) {
    int i = blockIdx.x * blockDim.x + threadIdx.x;
    if (i >= 81920) return;
    const float* Wo;
    const float* Wr;
    int nh, rem;
    if (i < 32768)      { Wo = W1o; Wr = W1r; nh = 128; rem = i; }
    else if (i < 65536) { Wo = W2o; Wr = W2r; nh = 128; rem = i - 32768; }
    else                { Wo = W3o; Wr = W3r; nh = 64;  rem = i - 65536; }
    int n = rem >> 7;
    int k = rem & 127;
    float v = (n < nh) ? Wo[(size_t)k * nh + n] : Wr[(size_t)k * nh + (n - nh)];
    __nv_bfloat16 hi = __float2bfloat16(v);
    g_Wh[i] = hi;
    g_Wl[i] = __float2bfloat16(v - __bfloat162float(hi));
}

// ---------------- CSR build --------------------------------------------------
__global__ void k_hist(const void* __restrict__ ei, int E) {
    int i = blockIdx.x * blockDim.x + threadIdx.x;
    if (i < E) atomicAdd(&g_deg[edge_at(ei, E + i)], 1);
}

__global__ void k_scanA(int n) {
    __shared__ int s[1024];
    int i = blockIdx.x * 1024 + threadIdx.x;
    int v = (i < n) ? g_deg[i] : 0;
    if (i < n) g_deginv[i] = 1.0f / (float)(v + 1);
    s[threadIdx.x] = v;
    __syncthreads();
    for (int off = 1; off < 1024; off <<= 1) {
        int t = (threadIdx.x >= off) ? s[threadIdx.x - off] : 0;
        __syncthreads();
        s[threadIdx.x] += t;
        __syncthreads();
    }
    if (i < n) g_ptr[i + 1] = s[threadIdx.x];
    if (threadIdx.x == 1023) g_bsum[blockIdx.x] = s[1023];
}

__global__ void k_scanB(int nb) {
    __shared__ int s[64];
    int t = threadIdx.x;
    int v = (t < nb) ? g_bsum[t] : 0;
    s[t] = v;
    __syncthreads();
    for (int off = 1; off < 64; off <<= 1) {
        int u = (t >= off) ? s[t - off] : 0;
        __syncthreads();
        s[t] += u;
        __syncthreads();
    }
    if (t < nb) g_bsum[t] = s[t] - v;   // exclusive
}

__global__ void k_scanC(int n) {
    int i = blockIdx.x * blockDim.x + threadIdx.x;
    if (i == 0) g_ptr[0] = 0;
    if (i < n) g_ptr[i + 1] += g_bsum[i >> 10];
}

__global__ void k_fill(const void* __restrict__ ei, int E) {
    int i = blockIdx.x * blockDim.x + threadIdx.x;
    if (i < E) {
        int r = edge_at(ei, i);
        int c = edge_at(ei, E + i);
        int pos = g_ptr[c] + atomicAdd(&g_fill[c], 1);
        g_src[pos] = r;
    }
}

// ---------------- bf16 helpers -----------------------------------------------
__device__ __forceinline__ unsigned packbf(float x, float y) {
    unsigned r;
    asm("cvt.rn.bf16x2.f32 %0, %1, %2;" : "=r"(r) : "f"(y), "f"(x));
    return r;
}
__device__ __forceinline__ void mma_bf16(float* c,
                                         unsigned a0, unsigned a1,
                                         unsigned a2, unsigned a3,
                                         unsigned b0, unsigned b1) {
    asm volatile(
        "mma.sync.aligned.m16n8k16.row.col.f32.bf16.bf16.f32 "
        "{%0,%1,%2,%3},{%4,%5,%6,%7},{%8,%9},{%0,%1,%2,%3};"
        : "+f"(c[0]), "+f"(c[1]), "+f"(c[2]), "+f"(c[3])
        : "r"(a0), "r"(a1), "r"(a2), "r"(a3), "r"(b0), "r"(b1));
}

#define SW 36   // smem stride (uints); fragment bank = 4*grp + q, conflict-free

// ---------------- GEMM: g_y[N][2*nhalf] = A[N][128] @ [Wout | Wroot] ---------
// bf16x3 compensated tensor-core GEMM. Block tile 128x128, BK=64, 8 warps
// (2x4), warp tile 64x32, mma m16n8k16.
__global__ __launch_bounds__(256)
void k_gemm_bf(const float* __restrict__ xin, int useH, int Woff,
               int nhalf, int N) {
    extern __shared__ unsigned smu[];
    unsigned* As_h = smu;
    unsigned* As_l = smu + 128 * SW;
    unsigned* Bs_h = smu + 2 * 128 * SW;
    unsigned* Bs_l = smu + 3 * 128 * SW;

    const float* A = useH ? (const float*)g_h : xin;

    const int tid = threadIdx.x;
    const int wid = tid >> 5;
    const int lane = tid & 31;
    const int grp = lane >> 2;
    const int q = lane & 3;
    const int warp_m = wid >> 2;    // 0..1
    const int warp_n = wid & 3;     // 0..3
    const int rowBase = blockIdx.y * 128;
    const int colBase = blockIdx.x * 128;
    const int Nc = 2 * nhalf;

    float acc[4][4][4];
#pragma unroll
    for (int i = 0; i < 4; i++)
#pragma unroll
        for (int j = 0; j < 4; j++)
#pragma unroll
            for (int v = 0; v < 4; v++) acc[i][j][v] = 0.0f;

    for (int kt = 0; kt < 128; kt += 64) {
        // ---- A tile: load float4 along k, split to hi/lo bf16x2 planes ----
#pragma unroll
        for (int l = 0; l < 8; l++) {
            int idx = l * 256 + tid;
            int r = idx >> 4;
            int c = (idx & 15) * 4;
            int grow = rowBase + r;
            float4 v = make_float4(0.f, 0.f, 0.f, 0.f);
            if (grow < N) v = *(const float4*)(A + (size_t)grow * 128 + kt + c);
            unsigned h0 = packbf(v.x, v.y);
            unsigned h1 = packbf(v.z, v.w);
            float lx = v.x - __uint_as_float(h0 << 16);
            float ly = v.y - __uint_as_float(h0 & 0xffff0000u);
            float lz = v.z - __uint_as_float(h1 << 16);
            float lw = v.w - __uint_as_float(h1 & 0xffff0000u);
            unsigned l0 = packbf(lx, ly);
            unsigned l1 = packbf(lz, lw);
            int off = r * SW + (c >> 1);
            *(uint2*)&As_h[off] = make_uint2(h0, h1);
            *(uint2*)&As_l[off] = make_uint2(l0, l1);
        }
        // ---- B tile: uint4 copies from pre-split g_Wh/g_Wl ----
#pragma unroll
        for (int l = 0; l < 8; l++) {
            int idx = l * 256 + tid;
            int plane = idx >> 10;
            int rem = idx & 1023;
            int n = rem >> 3;
            int jj = rem & 7;
            const __nv_bfloat16* Wp = plane ? g_Wl : g_Wh;
            const uint4* rowp =
                (const uint4*)(Wp + (size_t)(Woff + (colBase + n) * 128));
            uint4 v = rowp[(kt >> 3) + jj];
            unsigned* Bd = plane ? Bs_l : Bs_h;
            *(uint4*)&Bd[n * SW + jj * 4] = v;
        }
        __syncthreads();

#pragma unroll
        for (int ks = 0; ks < 4; ks++) {
            int kb = ks * 8;
            unsigned ah[4][4], al[4][4], bh[4][2], bl[4][2];
#pragma unroll
            for (int mf = 0; mf < 4; mf++) {
                int base = (warp_m * 64 + mf * 16 + grp) * SW + kb + q;
                ah[mf][0] = As_h[base];
                ah[mf][1] = As_h[base + 8 * SW];
                ah[mf][2] = As_h[base + 4];
                ah[mf][3] = As_h[base + 4 + 8 * SW];
                al[mf][0] = As_l[base];
                al[mf][1] = As_l[base + 8 * SW];
                al[mf][2] = As_l[base + 4];
                al[mf][3] = As_l[base + 4 + 8 * SW];
            }
#pragma unroll
            for (int nf = 0; nf < 4; nf++) {
                int cb = (warp_n * 32 + nf * 8 + grp) * SW + kb + q;
                bh[nf][0] = Bs_h[cb];
                bh[nf][1] = Bs_h[cb + 4];
                bl[nf][0] = Bs_l[cb];
                bl[nf][1] = Bs_l[cb + 4];
            }
#pragma unroll
            for (int mf = 0; mf < 4; mf++)
#pragma unroll
                for (int nf = 0; nf < 4; nf++) {
                    float* c = acc[mf][nf];
                    mma_bf16(c, ah[mf][0], ah[mf][1], ah[mf][2], ah[mf][3],
                             bh[nf][0], bh[nf][1]);
                    mma_bf16(c, ah[mf][0], ah[mf][1], ah[mf][2], ah[mf][3],
                             bl[nf][0], bl[nf][1]);
                    mma_bf16(c, al[mf][0], al[mf][1], al[mf][2], al[mf][3],
                             bh[nf][0], bh[nf][1]);
                }
        }
        __syncthreads();
    }

    // ---- epilogue ----
#pragma unroll
    for (int mf = 0; mf < 4; mf++) {
        int row0 = rowBase + warp_m * 64 + mf * 16 + grp;
        int row1 = row0 + 8;
#pragma unroll
        for (int nf = 0; nf < 4; nf++) {
            int col = colBase + warp_n * 32 + nf * 8 + 2 * q;
            float* c = acc[mf][nf];
            if (row0 < N)
                *(float2*)(g_y + (size_t)row0 * Nc + col) = make_float2(c[0], c[1]);
            if (row1 < N)
                *(float2*)(g_y + (size_t)row1 * Nc + col) = make_float2(c[2], c[3]);
        }
    }
}

// ---------------- Aggregation (warp per node), 128 cols ----------------------
// g_h = relu( deg_inv*(sum y_out[src] + y_out[w]) + y_root[w] + b )
__global__ __launch_bounds__(256)
void k_agg128(const float* __restrict__ bias, int N) {
    int w = (blockIdx.x * blockDim.x + threadIdx.x) >> 5;
    int lane = threadIdx.x & 31;
    if (w >= N) return;
    const float* Y = (const float*)g_y;
    size_t base = (size_t)w * 256;
    float4 acc = *(const float4*)(Y + base + lane * 4);   // self loop
    int p0 = g_ptr[w], p1 = g_ptr[w + 1];
    int e = p0;
    for (; e + 2 <= p1; e += 2) {
        int r0 = g_src[e], r1 = g_src[e + 1];
        float4 t0 = *(const float4*)(Y + (size_t)r0 * 256 + lane * 4);
        float4 t1 = *(const float4*)(Y + (size_t)r1 * 256 + lane * 4);
        acc.x += t0.x + t1.x; acc.y += t0.y + t1.y;
        acc.z += t0.z + t1.z; acc.w += t0.w + t1.w;
    }
    if (e < p1) {
        float4 t0 = *(const float4*)(Y + (size_t)g_src[e] * 256 + lane * 4);
        acc.x += t0.x; acc.y += t0.y; acc.z += t0.z; acc.w += t0.w;
    }
    float dinv = g_deginv[w];
    float4 rt = *(const float4*)(Y + base + 128 + lane * 4);
    float4 bv = *(const float4*)(bias + lane * 4);
    float4 o;
    o.x = fmaxf(acc.x * dinv + rt.x + bv.x, 0.f);
    o.y = fmaxf(acc.y * dinv + rt.y + bv.y, 0.f);
    o.z = fmaxf(acc.z * dinv + rt.z + bv.z, 0.f);
    o.w = fmaxf(acc.w * dinv + rt.w + bv.w, 0.f);
    *(float4*)(g_h + (size_t)w * 128 + lane * 4) = o;
}

// ---------------- Aggregation 64 cols + fused log_softmax --------------------
__global__ __launch_bounds__(256)
void k_agg64_lsm(const float* __restrict__ bias, float* __restrict__ Out, int N) {
    int w = (blockIdx.x * blockDim.x + threadIdx.x) >> 5;
    int lane = threadIdx.x & 31;
    if (w >= N) return;
    const float* Y = (const float*)g_y;
    size_t base = (size_t)w * 128;
    float2 acc = *(const float2*)(Y + base + lane * 2);   // self loop
    int p0 = g_ptr[w], p1 = g_ptr[w + 1];
    int e = p0;
    for (; e + 2 <= p1; e += 2) {
        int r0 = g_src[e], r1 = g_src[e + 1];
        float2 t0 = *(const float2*)(Y + (size_t)r0 * 128 + lane * 2);
        float2 t1 = *(const float2*)(Y + (size_t)r1 * 128 + lane * 2);
        acc.x += t0.x + t1.x; acc.y += t0.y + t1.y;
    }
    if (e < p1) {
        float2 t0 = *(const float2*)(Y + (size_t)g_src[e] * 128 + lane * 2);
        acc.x += t0.x; acc.y += t0.y;
    }
    float dinv = g_deginv[w];
    float2 rt = *(const float2*)(Y + base + 64 + lane * 2);
    float2 bv = *(const float2*)(bias + lane * 2);
    float v0 = fmaxf(acc.x * dinv + rt.x + bv.x, 0.f);
    float v1 = fmaxf(acc.y * dinv + rt.y + bv.y, 0.f);
    float m = fmaxf(v0, v1);
#pragma unroll
    for (int o = 16; o; o >>= 1) m = fmaxf(m, __shfl_xor_sync(0xffffffffu, m, o));
    float s = expf(v0 - m) + expf(v1 - m);
#pragma unroll
    for (int o = 16; o; o >>= 1) s += __shfl_xor_sync(0xffffffffu, s, o);
    float l = m + logf(s);
    *(float2*)(Out + (size_t)w * 64 + lane * 2) = make_float2(v0 - l, v1 - l);
}

// ---------------- driver -----------------------------------------------------
extern "C" void kernel_launch(void* const* d_in, const int* in_sizes, int n_in,
                              void* d_out, int out_size) {
    const float* x   = (const float*)d_in[0];
    const void*  ei  = d_in[1];
    const float* W1o = (const float*)d_in[2];
    const float* b1  = (const float*)d_in[3];
    const float* W1r = (const float*)d_in[4];
    const float* W2o = (const float*)d_in[5];
    const float* b2  = (const float*)d_in[6];
    const float* W2r = (const float*)d_in[7];
    const float* W3o = (const float*)d_in[8];
    const float* b3  = (const float*)d_in[9];
    const float* W3r = (const float*)d_in[10];
    float* out = (float*)d_out;

    int N = in_sizes[0] / 128;
    int E = in_sizes[1] / 2;

    const int smemBytes = 4 * 128 * SW * 4;   // 73728
    cudaFuncSetAttribute(k_gemm_bf, cudaFuncAttributeMaxDynamicSharedMemorySize,
                         smemBytes);

    int aggBlocks = (N * 32 + 255) / 256;
    dim3 g2(2, (N + 127) / 128);
    dim3 g1(1, (N + 127) / 128);
    int nb = (N + 1023) / 1024;

    // Launch order arranged so that the ncu capture (-s 5 -c 1) profiles the
    // layer-1 GEMM (launch index 5). k_gemm_bf(layer1) depends only on k_convW
    // and x, so it can legally run mid-CSR-build.
    k_convW<<<(81920 + 255) / 256, 256>>>(W1o, W1r, W2o, W2r, W3o, W3r);   // 0
    k_zero<<<(N + 255) / 256, 256>>>((const unsigned int*)ei, N);          // 1
    k_hist<<<(E + 255) / 256, 256>>>(ei, E);                               // 2
    k_scanA<<<nb, 1024>>>(N);                                              // 3
    k_scanB<<<1, 64>>>(nb);                                                // 4
    k_gemm_bf<<<g2, 256, smemBytes>>>(x, 0, 0, 128, N);                    // 5 <- profiled
    k_scanC<<<(N + 255) / 256, 256>>>(N);                                  // 6
    k_fill<<<(E + 255) / 256, 256>>>(ei, E);                               // 7

    // Layer 1 aggregation
    k_agg128<<<aggBlocks, 256>>>(b1, N);
    // Layer 2
    k_gemm_bf<<<g2, 256, smemBytes>>>(x, 1, 32768, 128, N);
    k_agg128<<<aggBlocks, 256>>>(b2, N);
    // Layer 3 (+ fused log_softmax)
    k_gemm_bf<<<g1, 256, smemBytes>>>(x, 1, 65536, 64, N);
    k_agg64_lsm<<<aggBlocks, 256>>>(b3, out, N);
}